// round 7
// baseline (speedup 1.0000x reference)
#include <cuda_runtime.h>
#include <cuda_bf16.h>
#include <math.h>
#include <stdint.h>

// Problem constants
#define B_    512
#define H_    512
#define OUT_  66
#define NCLS_ 12
#define INW_  78
#define G4_   2048          // 4*H_
#define LEN_  64
#define BH_   (B_*H_)

// Device scratch (static globals; no runtime allocation)
__device__ float g_Z0[B_ * G4_];            // step-0 additive term (permuted cols)
__device__ float g_Z [B_ * G4_];            // steps>=1 additive term (permuted cols)
__device__ float g_c [BH_];                 // cell state fp32 [b][u]
__device__ __nv_bfloat16 g_W1hi[G4_ * H_];  // W_hh split, rows permuted  [p][k]
__device__ __nv_bfloat16 g_W1lo[G4_ * H_];
__device__ __nv_bfloat16 g_W2hi[G4_ * H_];  // (W_hh + Wio@Wfc) split     [p][k]
__device__ __nv_bfloat16 g_W2lo[G4_ * H_];
__device__ __nv_bfloat16 g_h0hi[BH_];
__device__ __nv_bfloat16 g_h0lo[BH_];
__device__ __nv_bfloat16 g_Hhi[LEN_ * BH_]; // per-step hidden splits [t][b][u]
__device__ __nv_bfloat16 g_Hlo[LEN_ * BH_];

__device__ __forceinline__ float fsigm(float x) { return __frcp_rn(1.0f + __expf(-x)); }
__device__ __forceinline__ float ftanh(float x) { return 1.0f - 2.0f * __frcp_rn(1.0f + __expf(2.0f * x)); }

__device__ __forceinline__ uint32_t smem_u32(const void* p) {
    uint32_t a;
    asm("{ .reg .u64 t; cvta.to.shared.u64 t, %1; cvt.u32.u64 %0, t; }" : "=r"(a) : "l"(p));
    return a;
}
__device__ __forceinline__ void cp16(uint32_t dst, const void* src) {
    asm volatile("cp.async.cg.shared.global [%0], [%1], 16;" :: "r"(dst), "l"(src));
}
__device__ __forceinline__ void cp_commit() {
    asm volatile("cp.async.commit_group;" ::: "memory");
}
__device__ __forceinline__ void cp_wait1() {
    asm volatile("cp.async.wait_group 1;" ::: "memory");
}
__device__ __forceinline__ void ldsm_x4(uint32_t& r0, uint32_t& r1, uint32_t& r2, uint32_t& r3,
                                        uint32_t addr) {
    asm volatile("ldmatrix.sync.aligned.m8n8.x4.shared.b16 {%0,%1,%2,%3}, [%4];"
                 : "=r"(r0), "=r"(r1), "=r"(r2), "=r"(r3) : "r"(addr));
}
__device__ __forceinline__ void mma16816(float& c0, float& c1, float& c2, float& c3,
                                         uint32_t a0, uint32_t a1, uint32_t a2, uint32_t a3,
                                         uint32_t b0, uint32_t b1) {
    asm volatile(
        "mma.sync.aligned.m16n8k16.row.col.f32.bf16.bf16.f32 "
        "{%0,%1,%2,%3}, {%4,%5,%6,%7}, {%8,%9}, {%0,%1,%2,%3};"
        : "+f"(c0), "+f"(c1), "+f"(c2), "+f"(c3)
        : "r"(a0), "r"(a1), "r"(a2), "r"(a3), "r"(b0), "r"(b1));
}

// ---------------------------------------------------------------------------
// h0 = frame0 @ W_inh^T + b_inh (bf16-split) ; c0 = frame0 @ W_inc^T + b_inc
// ---------------------------------------------------------------------------
__global__ void k_prep_state(const float* __restrict__ inp,
                             const float* __restrict__ Winh, const float* __restrict__ binh,
                             const float* __restrict__ Winc, const float* __restrict__ binc) {
    int b = blockIdx.x;
    __shared__ float fr[OUT_];
    if (threadIdx.x < OUT_) fr[threadIdx.x] = inp[b * OUT_ + threadIdx.x];
    __syncthreads();
    for (int k = threadIdx.x; k < H_; k += blockDim.x) {
        float sh = binh[k], sc = binc[k];
        const float* wh = Winh + k * OUT_;
        const float* wc = Winc + k * OUT_;
        #pragma unroll 6
        for (int j = 0; j < OUT_; j++) {
            float f = fr[j];
            sh += f * wh[j];
            sc += f * wc[j];
        }
        __nv_bfloat16 hi = __float2bfloat16_rn(sh);
        g_h0hi[b * H_ + k] = hi;
        g_h0lo[b * H_ + k] = __float2bfloat16_rn(sh - __bfloat162float(hi));
        g_c[b * H_ + k] = sc;
    }
}

// ---------------------------------------------------------------------------
// Z (permuted columns p = u*4+gate)
// ---------------------------------------------------------------------------
__global__ void k_prep_Z(const float* __restrict__ W_ih,
                         const float* __restrict__ b_ih, const float* __restrict__ b_hh,
                         const float* __restrict__ b_fc,
                         const float* __restrict__ inp, const int* __restrict__ labels) {
    int n  = blockIdx.x * 256 + threadIdx.x;
    int p  = ((n & 511) << 2) | (n >> 9);
    int bb = blockIdx.y * 8;
    __shared__ float fr[8][OUT_];
    __shared__ float bf[OUT_];
    __shared__ int   lb[8];
    for (int x = threadIdx.x; x < 8 * OUT_; x += 256)
        fr[x / OUT_][x % OUT_] = inp[(bb + x / OUT_) * OUT_ + (x % OUT_)];
    if (threadIdx.x < OUT_) bf[threadIdx.x] = b_fc[threadIdx.x];
    if (threadIdx.x < 8)    lb[threadIdx.x] = labels[bb + threadIdx.x];
    __syncthreads();

    const float* w = W_ih + (size_t)n * INW_;
    float s1 = 0.0f;
    float a[8] = {0, 0, 0, 0, 0, 0, 0, 0};
    #pragma unroll 6
    for (int j = 0; j < OUT_; j++) {
        float wj = w[j];
        s1 += bf[j] * wj;
        #pragma unroll
        for (int i = 0; i < 8; i++) a[i] += fr[i][j] * wj;
    }
    float base = b_ih[n] + b_hh[n];
    #pragma unroll
    for (int i = 0; i < 8; i++) {
        int b = bb + i;
        float cls = w[OUT_ + lb[i]];
        g_Z0[(size_t)b * G4_ + p] = base + cls + a[i];
        g_Z [(size_t)b * G4_ + p] = base + cls + s1;
    }
}

// ---------------------------------------------------------------------------
// W splits, row-permuted, row-major [p][k]:
// W1 = W_hh ; W2 = W_hh + W_ih[:, :66] @ W_fc
// ---------------------------------------------------------------------------
__global__ void k_prep_W(const float* __restrict__ W_ih,
                         const float* __restrict__ W_hh,
                         const float* __restrict__ W_fc) {
    int n  = blockIdx.x * 256 + threadIdx.x;
    int p  = ((n & 511) << 2) | (n >> 9);
    int k0 = blockIdx.y * 8;
    __shared__ float wf[OUT_][8];
    for (int x = threadIdx.x; x < OUT_ * 8; x += 256)
        wf[x / 8][x % 8] = W_fc[(size_t)(x / 8) * H_ + k0 + (x % 8)];
    __syncthreads();

    const float* w = W_ih + (size_t)n * INW_;
    float a[8] = {0, 0, 0, 0, 0, 0, 0, 0};
    #pragma unroll 6
    for (int j = 0; j < OUT_; j++) {
        float wj = w[j];
        #pragma unroll
        for (int i = 0; i < 8; i++) a[i] += wj * wf[j][i];
    }
    #pragma unroll
    for (int i = 0; i < 8; i++) {
        int k = k0 + i;
        float w1 = W_hh[(size_t)n * H_ + k];
        float w2 = w1 + a[i];
        __nv_bfloat16 h1 = __float2bfloat16_rn(w1);
        __nv_bfloat16 h2 = __float2bfloat16_rn(w2);
        size_t o = (size_t)p * H_ + k;
        g_W1hi[o] = h1;
        g_W1lo[o] = __float2bfloat16_rn(w1 - __bfloat162float(h1));
        g_W2hi[o] = h2;
        g_W2lo[o] = __float2bfloat16_rn(w2 - __bfloat162float(h2));
    }
}

// ---------------------------------------------------------------------------
// HMMA fused step. CTA tile 128(m:batch) x 64(n:permuted gate cols), BK=64,
// 8 warps 4x2 (warp tile 32x32), mma.m16n8k16 bf16, 3 error-split passes,
// cp.async 3-stage pipeline. grid (32 n, 4 m) = 128 CTAs (one wave), 256 thr.
// ---------------------------------------------------------------------------
#define ASLAB 16384
#define BSLAB 8192
#define STEP_SMEM (3 * (ASLAB + BSLAB))     // 73728

__global__ __launch_bounds__(256) void k_step_mma(int t) {
    extern __shared__ __align__(16) char smem[];
    char* smA = smem;                        // 3 x 16KB
    char* smB = smem + 3 * ASLAB;            // 3 x 8KB

    const __nv_bfloat16* __restrict__ Ahi = (t == 0) ? g_h0hi : g_Hhi + (size_t)(t - 1) * BH_;
    const __nv_bfloat16* __restrict__ Alo = (t == 0) ? g_h0lo : g_Hlo + (size_t)(t - 1) * BH_;
    const __nv_bfloat16* __restrict__ Bhi = (t == 0) ? g_W1hi : g_W2hi;
    const __nv_bfloat16* __restrict__ Blo = (t == 0) ? g_W1lo : g_W2lo;
    const float* __restrict__ Zp = (t == 0) ? g_Z0 : g_Z;

    int tid  = threadIdx.x;
    int lane = tid & 31;
    int wid  = tid >> 5;
    int wr   = wid >> 1;          // warp m (0..3)
    int wc   = wid & 1;           // warp n (0..1)
    int n0   = blockIdx.x * 64;   // permuted col tile
    int m0   = blockIdx.y * 128;  // batch tile
    int u0   = n0 >> 2;

    // cp.async staging: A row = tid>>1 (128 rows, 64B/thread), B row = tid>>2 (64 rows, 32B/thread)
    int arow = tid >> 1, ahalf = tid & 1;
    int brow = tid >> 2, bq = tid & 3;
    uint32_t sA = smem_u32(smA);
    uint32_t sB = smem_u32(smB);
    uint32_t aDst = sA + (uint32_t)arow * 128u;
    uint32_t bDst = sB + (uint32_t)brow * 128u;

    float acc[2][4][4];
    #pragma unroll
    for (int i = 0; i < 2; i++)
        #pragma unroll
        for (int j = 0; j < 4; j++)
            #pragma unroll
            for (int q = 0; q < 4; q++) acc[i][j][q] = 0.0f;

    int lrowA = wr * 32 + (lane & 15);
    int lrowB = wc * 32 + (lane & 15);
    int lchunk = lane >> 4;

    // stage issuer: stage s (0..23): seg = s>>3 (split), kb = s&7 (k chunk)
    auto issue = [&](int s, int buf) {
        int seg = s >> 3, kb = s & 7;
        const __nv_bfloat16* As = (seg == 1) ? Alo : Ahi;
        const __nv_bfloat16* Bs = (seg == 2) ? Blo : Bhi;
        const __nv_bfloat16* ag = As + (size_t)(m0 + arow) * H_ + kb * 64;
        const __nv_bfloat16* bg = Bs + (size_t)(n0 + brow) * H_ + kb * 64;
        uint32_t ad = aDst + (uint32_t)buf * ASLAB;
        uint32_t bd = bDst + (uint32_t)buf * BSLAB;
        #pragma unroll
        for (int jj = 0; jj < 4; jj++) {
            int j = ahalf * 4 + jj;
            cp16(ad + (uint32_t)(((j ^ (arow & 7)) << 4)), ag + j * 8);
        }
        #pragma unroll
        for (int jj = 0; jj < 2; jj++) {
            int j = bq * 2 + jj;
            cp16(bd + (uint32_t)(((j ^ (brow & 7)) << 4)), bg + j * 8);
        }
        cp_commit();
    };

    issue(0, 0);
    issue(1, 1);

    int buf = 0;
    #pragma unroll 1
    for (int it = 0; it < 24; it++) {
        cp_wait1();
        __syncthreads();
        if (it + 2 < 24) {
            int nb = buf + 2; if (nb >= 3) nb -= 3;
            issue(it + 2, nb);
        }
        uint32_t aBase = sA + (uint32_t)buf * ASLAB;
        uint32_t bBase = sB + (uint32_t)buf * BSLAB;
        #pragma unroll
        for (int kc = 0; kc < 4; kc++) {
            uint32_t a[2][4], b[2][4];
            #pragma unroll
            for (int mb = 0; mb < 2; mb++) {
                int row = lrowA + mb * 16;
                uint32_t off = (uint32_t)row * 128u
                             + (uint32_t)(((2 * kc + lchunk) ^ (row & 7)) << 4);
                ldsm_x4(a[mb][0], a[mb][1], a[mb][2], a[mb][3], aBase + off);
            }
            #pragma unroll
            for (int nb2 = 0; nb2 < 2; nb2++) {
                int row = lrowB + nb2 * 16;
                uint32_t off = (uint32_t)row * 128u
                             + (uint32_t)(((2 * kc + lchunk) ^ (row & 7)) << 4);
                ldsm_x4(b[nb2][0], b[nb2][1], b[nb2][2], b[nb2][3], bBase + off);
            }
            #pragma unroll
            for (int mb = 0; mb < 2; mb++)
                #pragma unroll
                for (int j = 0; j < 4; j++) {
                    int nb2 = j >> 1, par = j & 1;
                    mma16816(acc[mb][j][0], acc[mb][j][1], acc[mb][j][2], acc[mb][j][3],
                             a[mb][0], a[mb][1], a[mb][2], a[mb][3],
                             b[nb2][par], b[nb2][par + 2]);
                }
        }
        if (++buf == 3) buf = 0;
    }

    // -------- fused LSTM epilogue --------
    bool even = (lane & 1) == 0;
    size_t toff = (size_t)t * BH_;
    #pragma unroll
    for (int mb = 0; mb < 2; mb++) {
        #pragma unroll
        for (int j = 0; j < 4; j++) {
            float d0 = acc[mb][j][0], d1 = acc[mb][j][1];
            float d2 = acc[mb][j][2], d3 = acc[mb][j][3];
            float x = __shfl_xor_sync(0xffffffffu, even ? d2 : d0, 1);
            float y = __shfl_xor_sync(0xffffffffu, even ? d3 : d1, 1);
            int r   = wr * 32 + mb * 16 + (lane >> 2) + (even ? 0 : 8);
            int ugl = wc * 8 + j * 2 + ((lane & 3) >> 1);
            float gi = even ? d0 : x;
            float gf = even ? d1 : y;
            float gg = even ? x : d2;
            float go = even ? y : d3;
            const float4 z = *(const float4*)(Zp + (size_t)(m0 + r) * G4_ + n0 + ugl * 4);
            gi += z.x; gf += z.y; gg += z.z; go += z.w;
            int ci = (m0 + r) * H_ + u0 + ugl;
            float c  = g_c[ci];
            float cn = fsigm(gf) * c + fsigm(gi) * ftanh(gg);
            float hn = fsigm(go) * ftanh(cn);
            g_c[ci] = cn;
            __nv_bfloat16 hi = __float2bfloat16_rn(hn);
            g_Hhi[toff + ci] = hi;
            g_Hlo[toff + ci] = __float2bfloat16_rn(hn - __bfloat162float(hi));
        }
    }
}

// ---------------------------------------------------------------------------
// Final: out[b,t,:] = (h_hi+h_lo)[t,b,:] @ W_fc^T + b_fc.  Warp per (t,b) row.
// ---------------------------------------------------------------------------
__global__ __launch_bounds__(256) void k_fc(float* __restrict__ out,
                                            const float* __restrict__ W_fc,
                                            const float* __restrict__ b_fc) {
    __shared__ float hs[8][H_];
    int w = threadIdx.x >> 5;
    int lane = threadIdx.x & 31;
    int r = blockIdx.x * 8 + w;                 // r = t*512 + b
    const uint4* hr = (const uint4*)(g_Hhi + (size_t)r * H_);
    const uint4* lr = (const uint4*)(g_Hlo + (size_t)r * H_);
    for (int x = lane; x < H_ / 8; x += 32) {
        uint4 a = hr[x], b = lr[x];
        const __nv_bfloat162* ap = (const __nv_bfloat162*)&a;
        const __nv_bfloat162* bp = (const __nv_bfloat162*)&b;
        float* d = &hs[w][x * 8];
        #pragma unroll
        for (int e = 0; e < 4; e++) {
            float2 fa = __bfloat1622float2(ap[e]);
            float2 fb = __bfloat1622float2(bp[e]);
            d[2 * e]     = fa.x + fb.x;
            d[2 * e + 1] = fa.y + fb.y;
        }
    }
    __syncwarp();

    int t = r >> 9;
    int b = r & 511;
    float* orow = out + ((size_t)b * LEN_ + t) * OUT_;
    const float4* hv = (const float4*)hs[w];
    for (int j = lane; j < OUT_; j += 32) {
        const float4* wrow = (const float4*)(W_fc + (size_t)j * H_);
        float s = 0.0f;
        #pragma unroll 8
        for (int x = 0; x < H_ / 4; x++) {
            float4 a = hv[x];
            float4 c = wrow[x];
            s += a.x * c.x + a.y * c.y + a.z * c.z + a.w * c.w;
        }
        orow[j] = s + b_fc[j];
    }
}

// ---------------------------------------------------------------------------
extern "C" void kernel_launch(void* const* d_in, const int* in_sizes, int n_in,
                              void* d_out, int out_size) {
    int off = (n_in >= 13) ? 1 : 0;   // 'length' scalar present
    const float* inputs = (const float*)d_in[0];
    const int*   labels = (const int*)  d_in[1];
    const float* W_ih  = (const float*)d_in[2 + off];
    const float* W_hh  = (const float*)d_in[3 + off];
    const float* b_ih  = (const float*)d_in[4 + off];
    const float* b_hh  = (const float*)d_in[5 + off];
    const float* W_fc  = (const float*)d_in[6 + off];
    const float* b_fc  = (const float*)d_in[7 + off];
    const float* W_inh = (const float*)d_in[8 + off];
    const float* b_inh = (const float*)d_in[9 + off];
    const float* W_inc = (const float*)d_in[10 + off];
    const float* b_inc = (const float*)d_in[11 + off];
    float* out = (float*)d_out;

    static bool attr_set = false;
    if (!attr_set) {
        cudaFuncSetAttribute(k_step_mma, cudaFuncAttributeMaxDynamicSharedMemorySize, STEP_SMEM);
        attr_set = true;
    }

    k_prep_state<<<B_, 256>>>(inputs, W_inh, b_inh, W_inc, b_inc);
    k_prep_Z<<<dim3(8, 64), 256>>>(W_ih, b_ih, b_hh, b_fc, inputs, labels);
    k_prep_W<<<dim3(8, 64), 256>>>(W_ih, W_hh, W_fc);

    for (int t = 0; t < LEN_; t++) {
        k_step_mma<<<dim3(32, 4), 256, STEP_SMEM>>>(t);
    }

    k_fc<<<(LEN_ * B_) / 8, 256>>>(out, W_fc, b_fc);
}

// round 8
// speedup vs baseline: 1.6748x; 1.6748x over previous
#include <cuda_runtime.h>
#include <cuda_bf16.h>
#include <math.h>
#include <stdint.h>

// Problem constants
#define B_    512
#define H_    512
#define OUT_  66
#define NCLS_ 12
#define INW_  78
#define G4_   2048          // 4*H_
#define LEN_  64
#define BH_   (B_*H_)
#define NCTA_ 128u

// Device scratch (static globals; no runtime allocation)
__device__ float g_Z0[B_ * G4_];            // step-0 additive term (permuted cols, W2-adjusted)
__device__ float g_Z [B_ * G4_];            // steps>=1 additive term (permuted cols)
__device__ float g_c [BH_];                 // initial cell state fp32 [b][u]
__device__ float g_h0f[BH_];                // h0 fp32 (for prep_q)
__device__ float g_q[B_ * OUT_];            // q = frame0 - h0 @ Wfc^T
__device__ __nv_bfloat16 g_W2hi[G4_ * H_];  // (W_hh + Wio@Wfc) split, rows permuted [p][k]
__device__ __nv_bfloat16 g_W2lo[G4_ * H_];
__device__ __nv_bfloat16 g_h0hi[BH_];
__device__ __nv_bfloat16 g_h0lo[BH_];
__device__ __nv_bfloat16 g_Hhi[LEN_ * BH_]; // per-step hidden splits [t][b][u]
__device__ __nv_bfloat16 g_Hlo[LEN_ * BH_];
__device__ unsigned int g_bar_ctr;          // grid barrier counter (reset by prep)

__device__ __forceinline__ float fsigm(float x) { return __frcp_rn(1.0f + __expf(-x)); }
__device__ __forceinline__ float ftanh(float x) { return 1.0f - 2.0f * __frcp_rn(1.0f + __expf(2.0f * x)); }

__device__ __forceinline__ uint32_t smem_u32(const void* p) {
    uint32_t a;
    asm("{ .reg .u64 t; cvta.to.shared.u64 t, %1; cvt.u32.u64 %0, t; }" : "=r"(a) : "l"(p));
    return a;
}
__device__ __forceinline__ void cp16(uint32_t dst, const void* src) {
    asm volatile("cp.async.cg.shared.global [%0], [%1], 16;" :: "r"(dst), "l"(src));
}
__device__ __forceinline__ void cp_commit() {
    asm volatile("cp.async.commit_group;" ::: "memory");
}
__device__ __forceinline__ void cp_wait1() {
    asm volatile("cp.async.wait_group 1;" ::: "memory");
}
__device__ __forceinline__ void cp_wait0() {
    asm volatile("cp.async.wait_group 0;" ::: "memory");
}
__device__ __forceinline__ void ldsm_x4(uint32_t& r0, uint32_t& r1, uint32_t& r2, uint32_t& r3,
                                        uint32_t addr) {
    asm volatile("ldmatrix.sync.aligned.m8n8.x4.shared.b16 {%0,%1,%2,%3}, [%4];"
                 : "=r"(r0), "=r"(r1), "=r"(r2), "=r"(r3) : "r"(addr));
}
__device__ __forceinline__ void mma16816(float& c0, float& c1, float& c2, float& c3,
                                         uint32_t a0, uint32_t a1, uint32_t a2, uint32_t a3,
                                         uint32_t b0, uint32_t b1) {
    asm volatile(
        "mma.sync.aligned.m16n8k16.row.col.f32.bf16.bf16.f32 "
        "{%0,%1,%2,%3}, {%4,%5,%6,%7}, {%8,%9}, {%0,%1,%2,%3};"
        : "+f"(c0), "+f"(c1), "+f"(c2), "+f"(c3)
        : "r"(a0), "r"(a1), "r"(a2), "r"(a3), "r"(b0), "r"(b1));
}

// ---------------------------------------------------------------------------
// h0 = frame0 @ W_inh^T + b_inh (fp32 + bf16-split) ; c0 = ... ; reset barrier
// ---------------------------------------------------------------------------
__global__ void k_prep_state(const float* __restrict__ inp,
                             const float* __restrict__ Winh, const float* __restrict__ binh,
                             const float* __restrict__ Winc, const float* __restrict__ binc) {
    int b = blockIdx.x;
    if (b == 0 && threadIdx.x == 0) g_bar_ctr = 0u;
    __shared__ float fr[OUT_];
    if (threadIdx.x < OUT_) fr[threadIdx.x] = inp[b * OUT_ + threadIdx.x];
    __syncthreads();
    for (int k = threadIdx.x; k < H_; k += blockDim.x) {
        float sh = binh[k], sc = binc[k];
        const float* wh = Winh + k * OUT_;
        const float* wc = Winc + k * OUT_;
        #pragma unroll 6
        for (int j = 0; j < OUT_; j++) {
            float f = fr[j];
            sh += f * wh[j];
            sc += f * wc[j];
        }
        __nv_bfloat16 hi = __float2bfloat16_rn(sh);
        g_h0f[b * H_ + k] = sh;
        g_h0hi[b * H_ + k] = hi;
        g_h0lo[b * H_ + k] = __float2bfloat16_rn(sh - __bfloat162float(hi));
        g_c[b * H_ + k] = sc;
    }
}

// ---------------------------------------------------------------------------
// q[b,j] = frame0[b,j] - (h0 @ W_fc^T)[b,j]      (allows step-0 to use W2)
// ---------------------------------------------------------------------------
__global__ void k_prep_q(const float* __restrict__ inp, const float* __restrict__ W_fc) {
    int b = blockIdx.x;
    __shared__ float h0s[H_];
    for (int k = threadIdx.x; k < H_; k += blockDim.x) h0s[k] = g_h0f[b * H_ + k];
    __syncthreads();
    int w = threadIdx.x >> 5, lane = threadIdx.x & 31;
    for (int j = w; j < OUT_; j += 8) {
        const float* wr = W_fc + (size_t)j * H_;
        float s = 0.0f;
        for (int k = lane; k < H_; k += 32) s += h0s[k] * wr[k];
        #pragma unroll
        for (int o = 16; o; o >>= 1) s += __shfl_xor_sync(0xffffffffu, s, o);
        if (lane == 0) g_q[b * OUT_ + j] = inp[b * OUT_ + j] - s;
    }
}

// ---------------------------------------------------------------------------
// Z (permuted columns p = u*4+gate):
// Z0[b,p] = base + cls + sum_j q[b,j]  * W_ih[n,j]    (W2-adjusted step 0)
// Z [b,p] = base + cls + sum_j b_fc[j] * W_ih[n,j]
// ---------------------------------------------------------------------------
__global__ void k_prep_Z(const float* __restrict__ W_ih,
                         const float* __restrict__ b_ih, const float* __restrict__ b_hh,
                         const float* __restrict__ b_fc,
                         const int* __restrict__ labels) {
    int n  = blockIdx.x * 256 + threadIdx.x;
    int p  = ((n & 511) << 2) | (n >> 9);
    int bb = blockIdx.y * 8;
    __shared__ float fr[8][OUT_];
    __shared__ float bf[OUT_];
    __shared__ int   lb[8];
    for (int x = threadIdx.x; x < 8 * OUT_; x += 256)
        fr[x / OUT_][x % OUT_] = g_q[(bb + x / OUT_) * OUT_ + (x % OUT_)];
    if (threadIdx.x < OUT_) bf[threadIdx.x] = b_fc[threadIdx.x];
    if (threadIdx.x < 8)    lb[threadIdx.x] = labels[bb + threadIdx.x];
    __syncthreads();

    const float* w = W_ih + (size_t)n * INW_;
    float s1 = 0.0f;
    float a[8] = {0, 0, 0, 0, 0, 0, 0, 0};
    #pragma unroll 6
    for (int j = 0; j < OUT_; j++) {
        float wj = w[j];
        s1 += bf[j] * wj;
        #pragma unroll
        for (int i = 0; i < 8; i++) a[i] += fr[i][j] * wj;
    }
    float base = b_ih[n] + b_hh[n];
    #pragma unroll
    for (int i = 0; i < 8; i++) {
        int b = bb + i;
        float cls = w[OUT_ + lb[i]];
        g_Z0[(size_t)b * G4_ + p] = base + cls + a[i];
        g_Z [(size_t)b * G4_ + p] = base + cls + s1;
    }
}

// ---------------------------------------------------------------------------
// W2 = W_hh + W_ih[:, :66] @ W_fc, bf16 hi/lo split, rows permuted [p][k]
// ---------------------------------------------------------------------------
__global__ void k_prep_W(const float* __restrict__ W_ih,
                         const float* __restrict__ W_hh,
                         const float* __restrict__ W_fc) {
    int n  = blockIdx.x * 256 + threadIdx.x;
    int p  = ((n & 511) << 2) | (n >> 9);
    int k0 = blockIdx.y * 8;
    __shared__ float wf[OUT_][8];
    for (int x = threadIdx.x; x < OUT_ * 8; x += 256)
        wf[x / 8][x % 8] = W_fc[(size_t)(x / 8) * H_ + k0 + (x % 8)];
    __syncthreads();

    const float* w = W_ih + (size_t)n * INW_;
    float a[8] = {0, 0, 0, 0, 0, 0, 0, 0};
    #pragma unroll 6
    for (int j = 0; j < OUT_; j++) {
        float wj = w[j];
        #pragma unroll
        for (int i = 0; i < 8; i++) a[i] += wj * wf[j][i];
    }
    #pragma unroll
    for (int i = 0; i < 8; i++) {
        int k = k0 + i;
        float w2 = W_hh[(size_t)n * H_ + k] + a[i];
        __nv_bfloat16 h2 = __float2bfloat16_rn(w2);
        size_t o = (size_t)p * H_ + k;
        g_W2hi[o] = h2;
        g_W2lo[o] = __float2bfloat16_rn(w2 - __bfloat162float(h2));
    }
}

// ---------------------------------------------------------------------------
// PERSISTENT kernel: all 64 LSTM steps. 128 CTAs (32 n-tiles x 4 m-tiles),
// 256 threads, 8 warps 4x2. W2 hi/lo resident in smem (128KB). Z, c in regs.
// Per step: 8 double-buffered cp.async A-chunks, 3-split HMMA, fused LSTM
// epilogue, software grid barrier.
// ---------------------------------------------------------------------------
#define SMB_  131072                      // B resident: 2 splits x 8 chunks x 8KB
#define SMA_  32768                       // A buffer: hi 16KB + lo 16KB
#define PS_SMEM (SMB_ + 2 * SMA_)         // 196608

__global__ __launch_bounds__(256) void k_persist() {
    extern __shared__ __align__(16) char smem[];
    char* smB = smem;
    char* smA = smem + SMB_;
    uint32_t sB = smem_u32(smB);
    uint32_t sA = smem_u32(smA);

    int tid = threadIdx.x, lane = tid & 31, wid = tid >> 5;
    int wr = wid >> 1, wc = wid & 1;
    int n0 = (int)(blockIdx.x & 31) * 64;
    int m0 = (int)(blockIdx.x >> 5) * 128;
    int u0 = n0 >> 2;

    // ---- load resident B (W2 hi/lo, swizzled) ----
    for (int u = tid; u < 8192; u += 256) {
        int s = u >> 12, rem = u & 4095;
        int kb = rem >> 9, r2 = rem & 511, row = r2 >> 3, j = r2 & 7;
        const __nv_bfloat16* src = (s ? g_W2lo : g_W2hi) + (size_t)(n0 + row) * H_ + kb * 64 + j * 8;
        uint32_t dst = sB + (uint32_t)(s * 65536 + kb * 8192 + row * 128 + (((j ^ (row & 7)) << 4)));
        cp16(dst, src);
    }
    cp_commit();
    cp_wait0();
    __syncthreads();

    // ---- per-thread epilogue constants: Z (t>=1) and c in registers ----
    bool even = (lane & 1) == 0;
    int rbase = wr * 32 + (lane >> 2) + (even ? 0 : 8);
    float4 zr[8];
    float  creg[8];
    #pragma unroll
    for (int mb = 0; mb < 2; mb++)
        #pragma unroll
        for (int j = 0; j < 4; j++) {
            int r = rbase + mb * 16;
            int ugl = wc * 8 + j * 2 + ((lane & 3) >> 1);
            zr[mb * 4 + j] = *(const float4*)(g_Z + (size_t)(m0 + r) * G4_ + n0 + ugl * 4);
            creg[mb * 4 + j] = g_c[(m0 + r) * H_ + u0 + ugl];
        }

    int arow = tid >> 1, ahalf = tid & 1;
    int lrowA = wr * 32 + (lane & 15);
    int lrowB = wc * 32 + (lane & 15);
    int lchunk = lane >> 4;

    #pragma unroll 1
    for (int t = 0; t < LEN_; t++) {
        const __nv_bfloat16* __restrict__ Ahi = (t == 0) ? g_h0hi : g_Hhi + (size_t)(t - 1) * BH_;
        const __nv_bfloat16* __restrict__ Alo = (t == 0) ? g_h0lo : g_Hlo + (size_t)(t - 1) * BH_;

        auto issueA = [&](int kb, int buf) {
            const __nv_bfloat16* ah = Ahi + (size_t)(m0 + arow) * H_ + kb * 64;
            const __nv_bfloat16* al = Alo + (size_t)(m0 + arow) * H_ + kb * 64;
            uint32_t ad = sA + (uint32_t)(buf * SMA_ + arow * 128);
            #pragma unroll
            for (int jj = 0; jj < 4; jj++) {
                int j = ahalf * 4 + jj;
                uint32_t off = (uint32_t)((j ^ (arow & 7)) << 4);
                cp16(ad + off, ah + j * 8);
                cp16(ad + 16384u + off, al + j * 8);
            }
            cp_commit();
        };

        float acc[2][4][4];
        #pragma unroll
        for (int i = 0; i < 2; i++)
            #pragma unroll
            for (int j = 0; j < 4; j++)
                #pragma unroll
                for (int q = 0; q < 4; q++) acc[i][j][q] = 0.0f;

        issueA(0, 0);
        issueA(1, 1);

        #pragma unroll 1
        for (int kb = 0; kb < 8; kb++) {
            if (kb < 7) cp_wait1(); else cp_wait0();
            __syncthreads();
            uint32_t aB = sA + (uint32_t)((kb & 1) * SMA_);
            uint32_t bB = sB + (uint32_t)(kb * 8192);
            #pragma unroll
            for (int kc = 0; kc < 4; kc++) {
                uint32_t ah[2][4], al[2][4], bh[2][4], bl[2][4];
                #pragma unroll
                for (int mb = 0; mb < 2; mb++) {
                    int row = lrowA + mb * 16;
                    uint32_t off = (uint32_t)row * 128u
                                 + (uint32_t)(((2 * kc + lchunk) ^ (row & 7)) << 4);
                    ldsm_x4(ah[mb][0], ah[mb][1], ah[mb][2], ah[mb][3], aB + off);
                    ldsm_x4(al[mb][0], al[mb][1], al[mb][2], al[mb][3], aB + 16384u + off);
                }
                #pragma unroll
                for (int nb2 = 0; nb2 < 2; nb2++) {
                    int row = lrowB + nb2 * 16;
                    uint32_t off = (uint32_t)row * 128u
                                 + (uint32_t)(((2 * kc + lchunk) ^ (row & 7)) << 4);
                    ldsm_x4(bh[nb2][0], bh[nb2][1], bh[nb2][2], bh[nb2][3], bB + off);
                    ldsm_x4(bl[nb2][0], bl[nb2][1], bl[nb2][2], bl[nb2][3], bB + 65536u + off);
                }
                #pragma unroll
                for (int mb = 0; mb < 2; mb++)
                    #pragma unroll
                    for (int j = 0; j < 4; j++) {
                        int nb2 = j >> 1, par = j & 1;
                        mma16816(acc[mb][j][0], acc[mb][j][1], acc[mb][j][2], acc[mb][j][3],
                                 ah[mb][0], ah[mb][1], ah[mb][2], ah[mb][3],
                                 bh[nb2][par], bh[nb2][par + 2]);
                        mma16816(acc[mb][j][0], acc[mb][j][1], acc[mb][j][2], acc[mb][j][3],
                                 al[mb][0], al[mb][1], al[mb][2], al[mb][3],
                                 bh[nb2][par], bh[nb2][par + 2]);
                        mma16816(acc[mb][j][0], acc[mb][j][1], acc[mb][j][2], acc[mb][j][3],
                                 ah[mb][0], ah[mb][1], ah[mb][2], ah[mb][3],
                                 bl[nb2][par], bl[nb2][par + 2]);
                    }
            }
            __syncthreads();
            if (kb + 2 < 8) issueA(kb + 2, kb & 1);
        }

        // ---- fused LSTM epilogue ----
        size_t toff = (size_t)t * BH_;
        #pragma unroll
        for (int mb = 0; mb < 2; mb++) {
            #pragma unroll
            for (int j = 0; j < 4; j++) {
                float d0 = acc[mb][j][0], d1 = acc[mb][j][1];
                float d2 = acc[mb][j][2], d3 = acc[mb][j][3];
                float x = __shfl_xor_sync(0xffffffffu, even ? d2 : d0, 1);
                float y = __shfl_xor_sync(0xffffffffu, even ? d3 : d1, 1);
                int r   = rbase + mb * 16;
                int ugl = wc * 8 + j * 2 + ((lane & 3) >> 1);
                float gi = even ? d0 : x;
                float gf = even ? d1 : y;
                float gg = even ? x : d2;
                float go = even ? y : d3;
                float4 z;
                if (t == 0) z = *(const float4*)(g_Z0 + (size_t)(m0 + r) * G4_ + n0 + ugl * 4);
                else        z = zr[mb * 4 + j];
                gi += z.x; gf += z.y; gg += z.z; go += z.w;
                float c  = creg[mb * 4 + j];
                float cn = fsigm(gf) * c + fsigm(gi) * ftanh(gg);
                float hn = fsigm(go) * ftanh(cn);
                creg[mb * 4 + j] = cn;
                int ci = (m0 + r) * H_ + u0 + ugl;
                __nv_bfloat16 hi = __float2bfloat16_rn(hn);
                g_Hhi[toff + ci] = hi;
                g_Hlo[toff + ci] = __float2bfloat16_rn(hn - __bfloat162float(hi));
            }
        }

        // ---- grid barrier (skip after last step) ----
        if (t < LEN_ - 1) {
            __syncthreads();
            if (tid == 0) {
                __threadfence();
                atomicAdd(&g_bar_ctr, 1u);
                unsigned int tgt = (unsigned int)(t + 1) * NCTA_;
                while (*(volatile unsigned int*)&g_bar_ctr < tgt) { }
                __threadfence();
            }
            __syncthreads();
        }
    }
}

// ---------------------------------------------------------------------------
// Final: out[b,t,:] = (h_hi+h_lo)[t,b,:] @ W_fc^T + b_fc.  Warp per (t,b) row.
// ---------------------------------------------------------------------------
__global__ __launch_bounds__(256) void k_fc(float* __restrict__ out,
                                            const float* __restrict__ W_fc,
                                            const float* __restrict__ b_fc) {
    __shared__ float hs[8][H_];
    int w = threadIdx.x >> 5;
    int lane = threadIdx.x & 31;
    int r = blockIdx.x * 8 + w;                 // r = t*512 + b
    const uint4* hr = (const uint4*)(g_Hhi + (size_t)r * H_);
    const uint4* lr = (const uint4*)(g_Hlo + (size_t)r * H_);
    for (int x = lane; x < H_ / 8; x += 32) {
        uint4 a = hr[x], b = lr[x];
        const __nv_bfloat162* ap = (const __nv_bfloat162*)&a;
        const __nv_bfloat162* bp = (const __nv_bfloat162*)&b;
        float* d = &hs[w][x * 8];
        #pragma unroll
        for (int e = 0; e < 4; e++) {
            float2 fa = __bfloat1622float2(ap[e]);
            float2 fb = __bfloat1622float2(bp[e]);
            d[2 * e]     = fa.x + fb.x;
            d[2 * e + 1] = fa.y + fb.y;
        }
    }
    __syncwarp();

    int t = r >> 9;
    int b = r & 511;
    float* orow = out + ((size_t)b * LEN_ + t) * OUT_;
    const float4* hv = (const float4*)hs[w];
    for (int j = lane; j < OUT_; j += 32) {
        const float4* wrow = (const float4*)(W_fc + (size_t)j * H_);
        float s = 0.0f;
        #pragma unroll 8
        for (int x = 0; x < H_ / 4; x++) {
            float4 a = hv[x];
            float4 c = wrow[x];
            s += a.x * c.x + a.y * c.y + a.z * c.z + a.w * c.w;
        }
        orow[j] = s + b_fc[j];
    }
}

// ---------------------------------------------------------------------------
extern "C" void kernel_launch(void* const* d_in, const int* in_sizes, int n_in,
                              void* d_out, int out_size) {
    int off = (n_in >= 13) ? 1 : 0;   // 'length' scalar present
    const float* inputs = (const float*)d_in[0];
    const int*   labels = (const int*)  d_in[1];
    const float* W_ih  = (const float*)d_in[2 + off];
    const float* W_hh  = (const float*)d_in[3 + off];
    const float* b_ih  = (const float*)d_in[4 + off];
    const float* b_hh  = (const float*)d_in[5 + off];
    const float* W_fc  = (const float*)d_in[6 + off];
    const float* b_fc  = (const float*)d_in[7 + off];
    const float* W_inh = (const float*)d_in[8 + off];
    const float* b_inh = (const float*)d_in[9 + off];
    const float* W_inc = (const float*)d_in[10 + off];
    const float* b_inc = (const float*)d_in[11 + off];
    float* out = (float*)d_out;

    cudaFuncSetAttribute(k_persist, cudaFuncAttributeMaxDynamicSharedMemorySize, PS_SMEM);

    k_prep_state<<<B_, 256>>>(inputs, W_inh, b_inh, W_inc, b_inc);
    k_prep_q<<<B_, 256>>>(inputs, W_fc);
    k_prep_Z<<<dim3(8, 64), 256>>>(W_ih, b_ih, b_hh, b_fc, labels);
    k_prep_W<<<dim3(8, 64), 256>>>(W_ih, W_hh, W_fc);

    k_persist<<<NCTA_, 256, PS_SMEM>>>();

    k_fc<<<(LEN_ * B_) / 8, 256>>>(out, W_fc, b_fc);
}

// round 9
// speedup vs baseline: 1.8095x; 1.0804x over previous
#include <cuda_runtime.h>
#include <cuda_bf16.h>
#include <math.h>
#include <stdint.h>

// Problem constants
#define B_    512
#define H_    512
#define OUT_  66
#define NCLS_ 12
#define INW_  78
#define G4_   2048          // 4*H_
#define LEN_  64
#define BH_   (B_*H_)
#define NCTA_ 128u

// Device scratch (static globals; no runtime allocation)
__device__ float g_Z0[B_ * G4_];            // step-0 additive term (permuted cols, W2-adjusted)
__device__ float g_Z [B_ * G4_];            // steps>=1 additive term (permuted cols)
__device__ float g_c [BH_];                 // initial cell state fp32 [b][u]
__device__ float g_q[B_ * OUT_];            // q = frame0 - h0 @ Wfc^T
__device__ float g_WihT[INW_ * G4_];        // W_ih transposed [j][n]
__device__ __nv_bfloat16 g_W2hi[G4_ * H_];  // (W_hh + Wio@Wfc) split, rows permuted [p][k]
__device__ __nv_bfloat16 g_W2lo[G4_ * H_];
__device__ __nv_bfloat16 g_h0hi[BH_];
__device__ __nv_bfloat16 g_h0lo[BH_];
__device__ __nv_bfloat16 g_Hhi[LEN_ * BH_]; // per-step hidden splits [t][b][u]
__device__ __nv_bfloat16 g_Hlo[LEN_ * BH_];
__device__ unsigned int g_barc[256];        // per-m-group barrier counters (stride 64)

__device__ __forceinline__ float fsigm(float x) { return __frcp_rn(1.0f + __expf(-x)); }
__device__ __forceinline__ float ftanh(float x) { return 1.0f - 2.0f * __frcp_rn(1.0f + __expf(2.0f * x)); }

__device__ __forceinline__ uint32_t smem_u32(const void* p) {
    uint32_t a;
    asm("{ .reg .u64 t; cvta.to.shared.u64 t, %1; cvt.u32.u64 %0, t; }" : "=r"(a) : "l"(p));
    return a;
}
__device__ __forceinline__ void cp16(uint32_t dst, const void* src) {
    asm volatile("cp.async.cg.shared.global [%0], [%1], 16;" :: "r"(dst), "l"(src));
}
__device__ __forceinline__ void cp_commit() {
    asm volatile("cp.async.commit_group;" ::: "memory");
}
__device__ __forceinline__ void cp_wait1() {
    asm volatile("cp.async.wait_group 1;" ::: "memory");
}
__device__ __forceinline__ void cp_wait0() {
    asm volatile("cp.async.wait_group 0;" ::: "memory");
}
__device__ __forceinline__ void ldsm_x4(uint32_t& r0, uint32_t& r1, uint32_t& r2, uint32_t& r3,
                                        uint32_t addr) {
    asm volatile("ldmatrix.sync.aligned.m8n8.x4.shared.b16 {%0,%1,%2,%3}, [%4];"
                 : "=r"(r0), "=r"(r1), "=r"(r2), "=r"(r3) : "r"(addr));
}
__device__ __forceinline__ void mma16816(float& c0, float& c1, float& c2, float& c3,
                                         uint32_t a0, uint32_t a1, uint32_t a2, uint32_t a3,
                                         uint32_t b0, uint32_t b1) {
    asm volatile(
        "mma.sync.aligned.m16n8k16.row.col.f32.bf16.bf16.f32 "
        "{%0,%1,%2,%3}, {%4,%5,%6,%7}, {%8,%9}, {%0,%1,%2,%3};"
        : "+f"(c0), "+f"(c1), "+f"(c2), "+f"(c3)
        : "r"(a0), "r"(a1), "r"(a2), "r"(a3), "r"(b0), "r"(b1));
}

// ---------------------------------------------------------------------------
// prep_a: blocks 0..511: h0/c0/splits + q for one batch row; blocks 512..575:
// W_ih transpose tiles. Also resets group barriers.
// ---------------------------------------------------------------------------
__global__ __launch_bounds__(256) void k_prep_a(const float* __restrict__ inp,
                                                const float* __restrict__ Winh, const float* __restrict__ binh,
                                                const float* __restrict__ Winc, const float* __restrict__ binc,
                                                const float* __restrict__ W_fc,
                                                const float* __restrict__ W_ih) {
    int bb = blockIdx.x;
    if (bb < B_) {
        if (bb == 0 && threadIdx.x < 4) g_barc[threadIdx.x * 64] = 0u;
        __shared__ float fr[OUT_];
        __shared__ float h0s[H_];
        if (threadIdx.x < OUT_) fr[threadIdx.x] = inp[bb * OUT_ + threadIdx.x];
        __syncthreads();
        for (int k = threadIdx.x; k < H_; k += blockDim.x) {
            float sh = binh[k], sc = binc[k];
            const float* wh = Winh + k * OUT_;
            const float* wc = Winc + k * OUT_;
            #pragma unroll 6
            for (int j = 0; j < OUT_; j++) {
                float f = fr[j];
                sh += f * wh[j];
                sc += f * wc[j];
            }
            __nv_bfloat16 hi = __float2bfloat16_rn(sh);
            h0s[k] = sh;
            g_h0hi[bb * H_ + k] = hi;
            g_h0lo[bb * H_ + k] = __float2bfloat16_rn(sh - __bfloat162float(hi));
            g_c[bb * H_ + k] = sc;
        }
        __syncthreads();
        int w = threadIdx.x >> 5, lane = threadIdx.x & 31;
        for (int j = w; j < OUT_; j += 8) {
            const float* wr = W_fc + (size_t)j * H_;
            float s = 0.0f;
            for (int k = lane; k < H_; k += 32) s += h0s[k] * wr[k];
            #pragma unroll
            for (int o = 16; o; o >>= 1) s += __shfl_xor_sync(0xffffffffu, s, o);
            if (lane == 0) g_q[bb * OUT_ + j] = fr[j] - s;
        }
    } else {
        // transpose tile: 32 n-rows x 78 j-cols
        int n0 = (bb - B_) * 32;
        __shared__ float ts[32 * INW_];
        for (int idx = threadIdx.x; idx < 32 * INW_; idx += 256)
            ts[idx] = W_ih[(size_t)n0 * INW_ + idx];
        __syncthreads();
        for (int idx = threadIdx.x; idx < 32 * INW_; idx += 256) {
            int j = idx >> 5, nn = idx & 31;
            g_WihT[(size_t)j * G4_ + n0 + nn] = ts[nn * INW_ + j];
        }
    }
}

// ---------------------------------------------------------------------------
// Z (permuted columns p = u*4+gate), coalesced via g_WihT:
// Z0[b,p] = base + cls + sum_j q[b,j]  * W_ih[n,j]
// Z [b,p] = base + cls + sum_j b_fc[j] * W_ih[n,j]
// ---------------------------------------------------------------------------
__global__ __launch_bounds__(256) void k_prep_Z(const float* __restrict__ b_ih,
                                                const float* __restrict__ b_hh,
                                                const float* __restrict__ b_fc,
                                                const int* __restrict__ labels) {
    int n  = blockIdx.x * 256 + threadIdx.x;
    int p  = ((n & 511) << 2) | (n >> 9);
    int bb = blockIdx.y * 8;
    __shared__ float fr[8][OUT_];
    __shared__ float bf[OUT_];
    __shared__ int   lb[8];
    for (int x = threadIdx.x; x < 8 * OUT_; x += 256)
        fr[x / OUT_][x % OUT_] = g_q[(bb + x / OUT_) * OUT_ + (x % OUT_)];
    if (threadIdx.x < OUT_) bf[threadIdx.x] = b_fc[threadIdx.x];
    if (threadIdx.x < 8)    lb[threadIdx.x] = labels[bb + threadIdx.x];
    __syncthreads();

    float s1 = 0.0f;
    float a[8] = {0, 0, 0, 0, 0, 0, 0, 0};
    #pragma unroll 6
    for (int j = 0; j < OUT_; j++) {
        float wj = g_WihT[(size_t)j * G4_ + n];
        s1 += bf[j] * wj;
        #pragma unroll
        for (int i = 0; i < 8; i++) a[i] += fr[i][j] * wj;
    }
    float base = b_ih[n] + b_hh[n];
    #pragma unroll
    for (int i = 0; i < 8; i++) {
        int b = bb + i;
        float cls = g_WihT[(size_t)(OUT_ + lb[i]) * G4_ + n];
        g_Z0[(size_t)b * G4_ + p] = base + cls + a[i];
        g_Z [(size_t)b * G4_ + p] = base + cls + s1;
    }
}

// ---------------------------------------------------------------------------
// W2 = W_hh + W_ih[:, :66] @ W_fc, bf16 hi/lo split, rows permuted [p][k]
// ---------------------------------------------------------------------------
__global__ __launch_bounds__(256) void k_prep_W(const float* __restrict__ W_hh,
                                                const float* __restrict__ W_fc) {
    int n  = blockIdx.x * 256 + threadIdx.x;
    int p  = ((n & 511) << 2) | (n >> 9);
    int k0 = blockIdx.y * 8;
    __shared__ float wf[OUT_][8];
    for (int x = threadIdx.x; x < OUT_ * 8; x += 256)
        wf[x / 8][x % 8] = W_fc[(size_t)(x / 8) * H_ + k0 + (x % 8)];
    __syncthreads();

    float a[8] = {0, 0, 0, 0, 0, 0, 0, 0};
    #pragma unroll 6
    for (int j = 0; j < OUT_; j++) {
        float wj = g_WihT[(size_t)j * G4_ + n];
        #pragma unroll
        for (int i = 0; i < 8; i++) a[i] += wj * wf[j][i];
    }
    #pragma unroll
    for (int i = 0; i < 8; i++) {
        int k = k0 + i;
        float w2 = W_hh[(size_t)n * H_ + k] + a[i];
        __nv_bfloat16 h2 = __float2bfloat16_rn(w2);
        size_t o = (size_t)p * H_ + k;
        g_W2hi[o] = h2;
        g_W2lo[o] = __float2bfloat16_rn(w2 - __bfloat162float(h2));
    }
}

// ---------------------------------------------------------------------------
// PERSISTENT kernel: 128 CTAs (32 n x 4 m-groups), 512 threads (16 warps 4x4),
// warp tile 32m x 16n. W2 hi/lo smem-resident (128KB). Triple-buffered A with
// prefetch-before-compute, 1 sync/chunk. Per-m-group software barriers.
// ---------------------------------------------------------------------------
#define SMB_  131072                      // B resident: 2 splits x 8 chunks x 8KB
#define SMA1  32768                       // one A buffer (hi 16KB + lo 16KB)
#define PS_SMEM (SMB_ + 3 * SMA1)         // 229376

__global__ __launch_bounds__(512) void k_persist() {
    extern __shared__ __align__(16) char smem[];
    uint32_t sB = smem_u32(smem);
    uint32_t sA = sB + SMB_;

    int tid = threadIdx.x, lane = tid & 31, wid = tid >> 5;
    int wr = wid >> 2, wc = wid & 3;
    int mg = (int)(blockIdx.x >> 5);
    int n0 = (int)(blockIdx.x & 31) * 64;
    int m0 = mg * 128;
    int u0 = n0 >> 2;

    // ---- load resident B (W2 hi/lo, swizzled) ----
    for (int u = tid; u < 8192; u += 512) {
        int s = u >> 12, rem = u & 4095;
        int kb = rem >> 9, r2 = rem & 511, row = r2 >> 3, j = r2 & 7;
        const __nv_bfloat16* src = (s ? g_W2lo : g_W2hi) + (size_t)(n0 + row) * H_ + kb * 64 + j * 8;
        uint32_t dst = sB + (uint32_t)(s * 65536 + kb * 8192 + row * 128 + ((j ^ (row & 7)) << 4));
        cp16(dst, src);
    }
    cp_commit();
    cp_wait0();
    __syncthreads();

    // ---- per-thread epilogue constants: Z (t>=1) and c in registers ----
    bool even = (lane & 1) == 0;
    int rbase = wr * 32 + (lane >> 2) + (even ? 0 : 8);
    float4 zr[4];
    float  creg[4];
    #pragma unroll
    for (int mb = 0; mb < 2; mb++)
        #pragma unroll
        for (int j = 0; j < 2; j++) {
            int r = rbase + mb * 16;
            int ugl = wc * 4 + j * 2 + ((lane & 3) >> 1);
            zr[mb * 2 + j] = *(const float4*)(g_Z + (size_t)(m0 + r) * G4_ + n0 + ugl * 4);
            creg[mb * 2 + j] = g_c[(m0 + r) * H_ + u0 + ugl];
        }

    int arow = tid >> 2, aq = tid & 3;
    int lrowA = wr * 32 + (lane & 15);
    int lrowB = wc * 16 + (lane & 15);
    int lch = lane >> 4;
    uint32_t aSw0 = (uint32_t)((aq     ^ (arow & 7)) << 4);
    uint32_t aSw1 = (uint32_t)(((aq+4) ^ (arow & 7)) << 4);

    #pragma unroll 1
    for (int t = 0; t < LEN_; t++) {
        const __nv_bfloat16* __restrict__ Ahi = (t == 0) ? g_h0hi : g_Hhi + (size_t)(t - 1) * BH_;
        const __nv_bfloat16* __restrict__ Alo = (t == 0) ? g_h0lo : g_Hlo + (size_t)(t - 1) * BH_;

        auto issueA = [&](int kb, int buf) {
            const __nv_bfloat16* ah = Ahi + (size_t)(m0 + arow) * H_ + kb * 64;
            const __nv_bfloat16* al = Alo + (size_t)(m0 + arow) * H_ + kb * 64;
            uint32_t ad = sA + (uint32_t)(buf * SMA1 + arow * 128);
            cp16(ad + aSw0,           ah + aq * 8);
            cp16(ad + aSw1,           ah + (aq + 4) * 8);
            cp16(ad + 16384u + aSw0,  al + aq * 8);
            cp16(ad + 16384u + aSw1,  al + (aq + 4) * 8);
            cp_commit();
        };

        float acc[2][2][4];
        #pragma unroll
        for (int i = 0; i < 2; i++)
            #pragma unroll
            for (int j = 0; j < 2; j++)
                #pragma unroll
                for (int q = 0; q < 4; q++) acc[i][j][q] = 0.0f;

        issueA(0, 0);
        issueA(1, 1);

        #pragma unroll 1
        for (int kb = 0; kb < 8; kb++) {
            if (kb < 7) cp_wait1(); else cp_wait0();
            __syncthreads();
            if (kb + 2 < 8) issueA(kb + 2, (kb + 2) % 3);

            uint32_t aB = sA + (uint32_t)((kb % 3) * SMA1);
            uint32_t bB = sB + (uint32_t)(kb * 8192);
            #pragma unroll
            for (int kc = 0; kc < 4; kc++) {
                uint32_t ah[2][4], al[2][4], bh[4], bl[4];
                #pragma unroll
                for (int mb = 0; mb < 2; mb++) {
                    int row = lrowA + mb * 16;
                    uint32_t off = (uint32_t)row * 128u
                                 + (uint32_t)(((2 * kc + lch) ^ (row & 7)) << 4);
                    ldsm_x4(ah[mb][0], ah[mb][1], ah[mb][2], ah[mb][3], aB + off);
                    ldsm_x4(al[mb][0], al[mb][1], al[mb][2], al[mb][3], aB + 16384u + off);
                }
                {
                    int row = lrowB;
                    uint32_t off = (uint32_t)row * 128u
                                 + (uint32_t)(((2 * kc + lch) ^ (row & 7)) << 4);
                    ldsm_x4(bh[0], bh[1], bh[2], bh[3], bB + off);
                    ldsm_x4(bl[0], bl[1], bl[2], bl[3], bB + 65536u + off);
                }
                // split-major MMA: stretch RAW distance per accumulator
                #pragma unroll
                for (int mb = 0; mb < 2; mb++)
                    #pragma unroll
                    for (int j = 0; j < 2; j++)
                        mma16816(acc[mb][j][0], acc[mb][j][1], acc[mb][j][2], acc[mb][j][3],
                                 ah[mb][0], ah[mb][1], ah[mb][2], ah[mb][3], bh[j], bh[j + 2]);
                #pragma unroll
                for (int mb = 0; mb < 2; mb++)
                    #pragma unroll
                    for (int j = 0; j < 2; j++)
                        mma16816(acc[mb][j][0], acc[mb][j][1], acc[mb][j][2], acc[mb][j][3],
                                 al[mb][0], al[mb][1], al[mb][2], al[mb][3], bh[j], bh[j + 2]);
                #pragma unroll
                for (int mb = 0; mb < 2; mb++)
                    #pragma unroll
                    for (int j = 0; j < 2; j++)
                        mma16816(acc[mb][j][0], acc[mb][j][1], acc[mb][j][2], acc[mb][j][3],
                                 ah[mb][0], ah[mb][1], ah[mb][2], ah[mb][3], bl[j], bl[j + 2]);
            }
        }

        // ---- fused LSTM epilogue ----
        size_t toff = (size_t)t * BH_;
        #pragma unroll
        for (int mb = 0; mb < 2; mb++) {
            #pragma unroll
            for (int j = 0; j < 2; j++) {
                float d0 = acc[mb][j][0], d1 = acc[mb][j][1];
                float d2 = acc[mb][j][2], d3 = acc[mb][j][3];
                float x = __shfl_xor_sync(0xffffffffu, even ? d2 : d0, 1);
                float y = __shfl_xor_sync(0xffffffffu, even ? d3 : d1, 1);
                int r   = rbase + mb * 16;
                int ugl = wc * 4 + j * 2 + ((lane & 3) >> 1);
                float gi = even ? d0 : x;
                float gf = even ? d1 : y;
                float gg = even ? x : d2;
                float go = even ? y : d3;
                float4 z;
                if (t == 0) z = *(const float4*)(g_Z0 + (size_t)(m0 + r) * G4_ + n0 + ugl * 4);
                else        z = zr[mb * 2 + j];
                gi += z.x; gf += z.y; gg += z.z; go += z.w;
                float c  = creg[mb * 2 + j];
                float cn = fsigm(gf) * c + fsigm(gi) * ftanh(gg);
                float hn = fsigm(go) * ftanh(cn);
                creg[mb * 2 + j] = cn;
                int ci = (m0 + r) * H_ + u0 + ugl;
                __nv_bfloat16 hi = __float2bfloat16_rn(hn);
                g_Hhi[toff + ci] = hi;
                g_Hlo[toff + ci] = __float2bfloat16_rn(hn - __bfloat162float(hi));
            }
        }

        // ---- per-m-group barrier (skip after last step) ----
        if (t < LEN_ - 1) {
            __syncthreads();
            if (tid == 0) {
                __threadfence();
                atomicAdd(&g_barc[mg * 64], 1u);
                unsigned int tgt = (unsigned int)(t + 1) * 32u;
                while (*(volatile unsigned int*)&g_barc[mg * 64] < tgt) { }
                __threadfence();
            }
            __syncthreads();
        }
    }
}

// ---------------------------------------------------------------------------
// Final: out[b,t,:] = (h_hi+h_lo)[t,b,:] @ W_fc^T + b_fc.  Warp per (t,b) row.
// ---------------------------------------------------------------------------
__global__ __launch_bounds__(256) void k_fc(float* __restrict__ out,
                                            const float* __restrict__ W_fc,
                                            const float* __restrict__ b_fc) {
    __shared__ float hs[8][H_];
    int w = threadIdx.x >> 5;
    int lane = threadIdx.x & 31;
    int r = blockIdx.x * 8 + w;                 // r = t*512 + b
    const uint4* hr = (const uint4*)(g_Hhi + (size_t)r * H_);
    const uint4* lr = (const uint4*)(g_Hlo + (size_t)r * H_);
    for (int x = lane; x < H_ / 8; x += 32) {
        uint4 a = hr[x], b = lr[x];
        const __nv_bfloat162* ap = (const __nv_bfloat162*)&a;
        const __nv_bfloat162* bp = (const __nv_bfloat162*)&b;
        float* d = &hs[w][x * 8];
        #pragma unroll
        for (int e = 0; e < 4; e++) {
            float2 fa = __bfloat1622float2(ap[e]);
            float2 fb = __bfloat1622float2(bp[e]);
            d[2 * e]     = fa.x + fb.x;
            d[2 * e + 1] = fa.y + fb.y;
        }
    }
    __syncwarp();

    int t = r >> 9;
    int b = r & 511;
    float* orow = out + ((size_t)b * LEN_ + t) * OUT_;
    const float4* hv = (const float4*)hs[w];
    for (int j = lane; j < OUT_; j += 32) {
        const float4* wrow = (const float4*)(W_fc + (size_t)j * H_);
        float s = 0.0f;
        #pragma unroll 8
        for (int x = 0; x < H_ / 4; x++) {
            float4 a = hv[x];
            float4 c = wrow[x];
            s += a.x * c.x + a.y * c.y + a.z * c.z + a.w * c.w;
        }
        orow[j] = s + b_fc[j];
    }
}

// ---------------------------------------------------------------------------
extern "C" void kernel_launch(void* const* d_in, const int* in_sizes, int n_in,
                              void* d_out, int out_size) {
    int off = (n_in >= 13) ? 1 : 0;   // 'length' scalar present
    const float* inputs = (const float*)d_in[0];
    const int*   labels = (const int*)  d_in[1];
    const float* W_ih  = (const float*)d_in[2 + off];
    const float* W_hh  = (const float*)d_in[3 + off];
    const float* b_ih  = (const float*)d_in[4 + off];
    const float* b_hh  = (const float*)d_in[5 + off];
    const float* W_fc  = (const float*)d_in[6 + off];
    const float* b_fc  = (const float*)d_in[7 + off];
    const float* W_inh = (const float*)d_in[8 + off];
    const float* b_inh = (const float*)d_in[9 + off];
    const float* W_inc = (const float*)d_in[10 + off];
    const float* b_inc = (const float*)d_in[11 + off];
    float* out = (float*)d_out;

    cudaFuncSetAttribute(k_persist, cudaFuncAttributeMaxDynamicSharedMemorySize, PS_SMEM);

    k_prep_a<<<B_ + 64, 256>>>(inputs, W_inh, b_inh, W_inc, b_inc, W_fc, W_ih);
    k_prep_Z<<<dim3(8, 64), 256>>>(b_ih, b_hh, b_fc, labels);
    k_prep_W<<<dim3(8, 64), 256>>>(W_hh, W_fc);

    k_persist<<<NCTA_, 512, PS_SMEM>>>();

    k_fc<<<(LEN_ * B_) / 8, 256>>>(out, W_fc, b_fc);
}

// round 10
// speedup vs baseline: 3.3593x; 1.8565x over previous
#include <cuda_runtime.h>
#include <cuda_bf16.h>
#include <math.h>
#include <stdint.h>

// Problem constants
#define B_    512
#define H_    512
#define OUT_  66
#define NCLS_ 12
#define INW_  78
#define G4_   2048          // 4*H_
#define LEN_  64
#define BH_   (B_*H_)
#define NCTA_ 128u

// Device scratch (static globals; no runtime allocation)
__device__ float g_Z0[B_ * G4_];            // step-0 additive term (permuted cols, W2-adjusted)
__device__ float g_Z [B_ * G4_];            // steps>=1 additive term (permuted cols)
__device__ float g_c [BH_];                 // initial cell state fp32 [b][u]
__device__ float g_q[B_ * OUT_];            // q = frame0 - h0 @ Wfc^T
__device__ float g_WihT[INW_ * G4_];        // W_ih transposed [j][n]
__device__ __nv_bfloat16 g_W2hi[G4_ * H_];  // (W_hh + Wio@Wfc) split, rows permuted [p][k]
__device__ __nv_bfloat16 g_W2lo[G4_ * H_];
__device__ __nv_bfloat16 g_Wfchi[80 * H_];  // W_fc split, padded to 80 rows
__device__ __nv_bfloat16 g_Wfclo[80 * H_];
__device__ __nv_bfloat16 g_h0hi[BH_];
__device__ __nv_bfloat16 g_h0lo[BH_];
__device__ __nv_bfloat16 g_Hhi[LEN_ * BH_]; // per-step hidden splits [t][b][u]
__device__ __nv_bfloat16 g_Hlo[LEN_ * BH_];
__device__ unsigned int g_barc[256];        // per-m-group barrier counters (stride 64)

__device__ __forceinline__ float fsigm(float x) { return __frcp_rn(1.0f + __expf(-x)); }
__device__ __forceinline__ float ftanh(float x) { return 1.0f - 2.0f * __frcp_rn(1.0f + __expf(2.0f * x)); }

__device__ __forceinline__ uint32_t smem_u32(const void* p) {
    uint32_t a;
    asm("{ .reg .u64 t; cvta.to.shared.u64 t, %1; cvt.u32.u64 %0, t; }" : "=r"(a) : "l"(p));
    return a;
}
__device__ __forceinline__ void cp16(uint32_t dst, const void* src) {
    asm volatile("cp.async.cg.shared.global [%0], [%1], 16;" :: "r"(dst), "l"(src));
}
__device__ __forceinline__ void cp_commit() {
    asm volatile("cp.async.commit_group;" ::: "memory");
}
__device__ __forceinline__ void cp_wait1() {
    asm volatile("cp.async.wait_group 1;" ::: "memory");
}
__device__ __forceinline__ void cp_wait0() {
    asm volatile("cp.async.wait_group 0;" ::: "memory");
}
__device__ __forceinline__ void ldsm_x4(uint32_t& r0, uint32_t& r1, uint32_t& r2, uint32_t& r3,
                                        uint32_t addr) {
    asm volatile("ldmatrix.sync.aligned.m8n8.x4.shared.b16 {%0,%1,%2,%3}, [%4];"
                 : "=r"(r0), "=r"(r1), "=r"(r2), "=r"(r3) : "r"(addr));
}
__device__ __forceinline__ void mma16816(float& c0, float& c1, float& c2, float& c3,
                                         uint32_t a0, uint32_t a1, uint32_t a2, uint32_t a3,
                                         uint32_t b0, uint32_t b1) {
    asm volatile(
        "mma.sync.aligned.m16n8k16.row.col.f32.bf16.bf16.f32 "
        "{%0,%1,%2,%3}, {%4,%5,%6,%7}, {%8,%9}, {%0,%1,%2,%3};"
        : "+f"(c0), "+f"(c1), "+f"(c2), "+f"(c3)
        : "r"(a0), "r"(a1), "r"(a2), "r"(a3), "r"(b0), "r"(b1));
}

// ---------------------------------------------------------------------------
// prep_a: blocks 0..511: h0/c0/splits + q for one batch row; blocks 512..575:
// W_ih transpose tiles. Also resets group barriers.
// ---------------------------------------------------------------------------
__global__ __launch_bounds__(256) void k_prep_a(const float* __restrict__ inp,
                                                const float* __restrict__ Winh, const float* __restrict__ binh,
                                                const float* __restrict__ Winc, const float* __restrict__ binc,
                                                const float* __restrict__ W_fc,
                                                const float* __restrict__ W_ih) {
    int bb = blockIdx.x;
    if (bb < B_) {
        if (bb == 0 && threadIdx.x < 4) g_barc[threadIdx.x * 64] = 0u;
        __shared__ float fr[OUT_];
        __shared__ float h0s[H_];
        if (threadIdx.x < OUT_) fr[threadIdx.x] = inp[bb * OUT_ + threadIdx.x];
        __syncthreads();
        for (int k = threadIdx.x; k < H_; k += blockDim.x) {
            float sh = binh[k], sc = binc[k];
            const float* wh = Winh + k * OUT_;
            const float* wc = Winc + k * OUT_;
            #pragma unroll 6
            for (int j = 0; j < OUT_; j++) {
                float f = fr[j];
                sh += f * wh[j];
                sc += f * wc[j];
            }
            __nv_bfloat16 hi = __float2bfloat16_rn(sh);
            h0s[k] = sh;
            g_h0hi[bb * H_ + k] = hi;
            g_h0lo[bb * H_ + k] = __float2bfloat16_rn(sh - __bfloat162float(hi));
            g_c[bb * H_ + k] = sc;
        }
        __syncthreads();
        int w = threadIdx.x >> 5, lane = threadIdx.x & 31;
        for (int j = w; j < OUT_; j += 8) {
            const float* wr = W_fc + (size_t)j * H_;
            float s = 0.0f;
            for (int k = lane; k < H_; k += 32) s += h0s[k] * wr[k];
            #pragma unroll
            for (int o = 16; o; o >>= 1) s += __shfl_xor_sync(0xffffffffu, s, o);
            if (lane == 0) g_q[bb * OUT_ + j] = fr[j] - s;
        }
    } else {
        // transpose tile: 32 n-rows x 78 j-cols
        int n0 = (bb - B_) * 32;
        __shared__ float ts[32 * INW_];
        for (int idx = threadIdx.x; idx < 32 * INW_; idx += 256)
            ts[idx] = W_ih[(size_t)n0 * INW_ + idx];
        __syncthreads();
        for (int idx = threadIdx.x; idx < 32 * INW_; idx += 256) {
            int j = idx >> 5, nn = idx & 31;
            g_WihT[(size_t)j * G4_ + n0 + nn] = ts[nn * INW_ + j];
        }
    }
}

// ---------------------------------------------------------------------------
// W_fc bf16 hi/lo split, zero-padded to 80 rows. grid 80, block 256.
// ---------------------------------------------------------------------------
__global__ __launch_bounds__(256) void k_prep_fc(const float* __restrict__ W_fc) {
    int j = blockIdx.x;
    for (int k = threadIdx.x; k < H_; k += 256) {
        float v = (j < OUT_) ? W_fc[(size_t)j * H_ + k] : 0.0f;
        __nv_bfloat16 hi = __float2bfloat16_rn(v);
        g_Wfchi[(size_t)j * H_ + k] = hi;
        g_Wfclo[(size_t)j * H_ + k] = __float2bfloat16_rn(v - __bfloat162float(hi));
    }
}

// ---------------------------------------------------------------------------
// Z (permuted columns p = u*4+gate), coalesced via g_WihT
// ---------------------------------------------------------------------------
__global__ __launch_bounds__(256) void k_prep_Z(const float* __restrict__ b_ih,
                                                const float* __restrict__ b_hh,
                                                const float* __restrict__ b_fc,
                                                const int* __restrict__ labels) {
    int n  = blockIdx.x * 256 + threadIdx.x;
    int p  = ((n & 511) << 2) | (n >> 9);
    int bb = blockIdx.y * 8;
    __shared__ float fr[8][OUT_];
    __shared__ float bf[OUT_];
    __shared__ int   lb[8];
    for (int x = threadIdx.x; x < 8 * OUT_; x += 256)
        fr[x / OUT_][x % OUT_] = g_q[(bb + x / OUT_) * OUT_ + (x % OUT_)];
    if (threadIdx.x < OUT_) bf[threadIdx.x] = b_fc[threadIdx.x];
    if (threadIdx.x < 8)    lb[threadIdx.x] = labels[bb + threadIdx.x];
    __syncthreads();

    float s1 = 0.0f;
    float a[8] = {0, 0, 0, 0, 0, 0, 0, 0};
    #pragma unroll 6
    for (int j = 0; j < OUT_; j++) {
        float wj = g_WihT[(size_t)j * G4_ + n];
        s1 += bf[j] * wj;
        #pragma unroll
        for (int i = 0; i < 8; i++) a[i] += fr[i][j] * wj;
    }
    float base = b_ih[n] + b_hh[n];
    #pragma unroll
    for (int i = 0; i < 8; i++) {
        int b = bb + i;
        float cls = g_WihT[(size_t)(OUT_ + lb[i]) * G4_ + n];
        g_Z0[(size_t)b * G4_ + p] = base + cls + a[i];
        g_Z [(size_t)b * G4_ + p] = base + cls + s1;
    }
}

// ---------------------------------------------------------------------------
// W2 = W_hh + W_ih[:, :66] @ W_fc, bf16 hi/lo split, rows permuted [p][k]
// ---------------------------------------------------------------------------
__global__ __launch_bounds__(256) void k_prep_W(const float* __restrict__ W_hh,
                                                const float* __restrict__ W_fc) {
    int n  = blockIdx.x * 256 + threadIdx.x;
    int p  = ((n & 511) << 2) | (n >> 9);
    int k0 = blockIdx.y * 8;
    __shared__ float wf[OUT_][8];
    for (int x = threadIdx.x; x < OUT_ * 8; x += 256)
        wf[x / 8][x % 8] = W_fc[(size_t)(x / 8) * H_ + k0 + (x % 8)];
    __syncthreads();

    float a[8] = {0, 0, 0, 0, 0, 0, 0, 0};
    #pragma unroll 6
    for (int j = 0; j < OUT_; j++) {
        float wj = g_WihT[(size_t)j * G4_ + n];
        #pragma unroll
        for (int i = 0; i < 8; i++) a[i] += wj * wf[j][i];
    }
    #pragma unroll
    for (int i = 0; i < 8; i++) {
        int k = k0 + i;
        float w2 = W_hh[(size_t)n * H_ + k] + a[i];
        __nv_bfloat16 h2 = __float2bfloat16_rn(w2);
        size_t o = (size_t)p * H_ + k;
        g_W2hi[o] = h2;
        g_W2lo[o] = __float2bfloat16_rn(w2 - __bfloat162float(h2));
    }
}

// ---------------------------------------------------------------------------
// PERSISTENT kernel: 128 CTAs (32 n x 4 m-groups), 512 threads (16 warps 4x4),
// warp tile 32m x 16n. W2 hi/lo smem-resident (128KB). Triple-buffered A with
// prefetch-before-compute, 1 sync/chunk. Per-m-group software barriers.
// ---------------------------------------------------------------------------
#define SMB_  131072                      // B resident: 2 splits x 8 chunks x 8KB
#define SMA1  32768                       // one A buffer (hi 16KB + lo 16KB)
#define PS_SMEM (SMB_ + 3 * SMA1)         // 229376

__global__ __launch_bounds__(512) void k_persist() {
    extern __shared__ __align__(16) char smem[];
    uint32_t sB = smem_u32(smem);
    uint32_t sA = sB + SMB_;

    int tid = threadIdx.x, lane = tid & 31, wid = tid >> 5;
    int wr = wid >> 2, wc = wid & 3;
    int mg = (int)(blockIdx.x >> 5);
    int n0 = (int)(blockIdx.x & 31) * 64;
    int m0 = mg * 128;
    int u0 = n0 >> 2;

    // ---- load resident B (W2 hi/lo, swizzled) ----
    for (int u = tid; u < 8192; u += 512) {
        int s = u >> 12, rem = u & 4095;
        int kb = rem >> 9, r2 = rem & 511, row = r2 >> 3, j = r2 & 7;
        const __nv_bfloat16* src = (s ? g_W2lo : g_W2hi) + (size_t)(n0 + row) * H_ + kb * 64 + j * 8;
        uint32_t dst = sB + (uint32_t)(s * 65536 + kb * 8192 + row * 128 + ((j ^ (row & 7)) << 4));
        cp16(dst, src);
    }
    cp_commit();
    cp_wait0();
    __syncthreads();

    // ---- per-thread epilogue constants: Z (t>=1) and c in registers ----
    bool even = (lane & 1) == 0;
    int rbase = wr * 32 + (lane >> 2) + (even ? 0 : 8);
    float4 zr[4];
    float  creg[4];
    #pragma unroll
    for (int mb = 0; mb < 2; mb++)
        #pragma unroll
        for (int j = 0; j < 2; j++) {
            int r = rbase + mb * 16;
            int ugl = wc * 4 + j * 2 + ((lane & 3) >> 1);
            zr[mb * 2 + j] = *(const float4*)(g_Z + (size_t)(m0 + r) * G4_ + n0 + ugl * 4);
            creg[mb * 2 + j] = g_c[(m0 + r) * H_ + u0 + ugl];
        }

    int arow = tid >> 2, aq = tid & 3;
    int lrowA = wr * 32 + (lane & 15);
    int lrowB = wc * 16 + (lane & 15);
    int lch = lane >> 4;
    uint32_t aSw0 = (uint32_t)((aq     ^ (arow & 7)) << 4);
    uint32_t aSw1 = (uint32_t)(((aq+4) ^ (arow & 7)) << 4);

    #pragma unroll 1
    for (int t = 0; t < LEN_; t++) {
        const __nv_bfloat16* __restrict__ Ahi = (t == 0) ? g_h0hi : g_Hhi + (size_t)(t - 1) * BH_;
        const __nv_bfloat16* __restrict__ Alo = (t == 0) ? g_h0lo : g_Hlo + (size_t)(t - 1) * BH_;

        auto issueA = [&](int kb, int buf) {
            const __nv_bfloat16* ah = Ahi + (size_t)(m0 + arow) * H_ + kb * 64;
            const __nv_bfloat16* al = Alo + (size_t)(m0 + arow) * H_ + kb * 64;
            uint32_t ad = sA + (uint32_t)(buf * SMA1 + arow * 128);
            cp16(ad + aSw0,           ah + aq * 8);
            cp16(ad + aSw1,           ah + (aq + 4) * 8);
            cp16(ad + 16384u + aSw0,  al + aq * 8);
            cp16(ad + 16384u + aSw1,  al + (aq + 4) * 8);
            cp_commit();
        };

        float acc[2][2][4];
        #pragma unroll
        for (int i = 0; i < 2; i++)
            #pragma unroll
            for (int j = 0; j < 2; j++)
                #pragma unroll
                for (int q = 0; q < 4; q++) acc[i][j][q] = 0.0f;

        issueA(0, 0);
        issueA(1, 1);

        #pragma unroll 1
        for (int kb = 0; kb < 8; kb++) {
            if (kb < 7) cp_wait1(); else cp_wait0();
            __syncthreads();
            if (kb + 2 < 8) issueA(kb + 2, (kb + 2) % 3);

            uint32_t aB = sA + (uint32_t)((kb % 3) * SMA1);
            uint32_t bB = sB + (uint32_t)(kb * 8192);
            #pragma unroll
            for (int kc = 0; kc < 4; kc++) {
                uint32_t ah[2][4], al[2][4], bh[4], bl[4];
                #pragma unroll
                for (int mb = 0; mb < 2; mb++) {
                    int row = lrowA + mb * 16;
                    uint32_t off = (uint32_t)row * 128u
                                 + (uint32_t)(((2 * kc + lch) ^ (row & 7)) << 4);
                    ldsm_x4(ah[mb][0], ah[mb][1], ah[mb][2], ah[mb][3], aB + off);
                    ldsm_x4(al[mb][0], al[mb][1], al[mb][2], al[mb][3], aB + 16384u + off);
                }
                {
                    int row = lrowB;
                    uint32_t off = (uint32_t)row * 128u
                                 + (uint32_t)(((2 * kc + lch) ^ (row & 7)) << 4);
                    ldsm_x4(bh[0], bh[1], bh[2], bh[3], bB + off);
                    ldsm_x4(bl[0], bl[1], bl[2], bl[3], bB + 65536u + off);
                }
                #pragma unroll
                for (int mb = 0; mb < 2; mb++)
                    #pragma unroll
                    for (int j = 0; j < 2; j++)
                        mma16816(acc[mb][j][0], acc[mb][j][1], acc[mb][j][2], acc[mb][j][3],
                                 ah[mb][0], ah[mb][1], ah[mb][2], ah[mb][3], bh[j], bh[j + 2]);
                #pragma unroll
                for (int mb = 0; mb < 2; mb++)
                    #pragma unroll
                    for (int j = 0; j < 2; j++)
                        mma16816(acc[mb][j][0], acc[mb][j][1], acc[mb][j][2], acc[mb][j][3],
                                 al[mb][0], al[mb][1], al[mb][2], al[mb][3], bh[j], bh[j + 2]);
                #pragma unroll
                for (int mb = 0; mb < 2; mb++)
                    #pragma unroll
                    for (int j = 0; j < 2; j++)
                        mma16816(acc[mb][j][0], acc[mb][j][1], acc[mb][j][2], acc[mb][j][3],
                                 ah[mb][0], ah[mb][1], ah[mb][2], ah[mb][3], bl[j], bl[j + 2]);
            }
        }

        // ---- fused LSTM epilogue ----
        size_t toff = (size_t)t * BH_;
        #pragma unroll
        for (int mb = 0; mb < 2; mb++) {
            #pragma unroll
            for (int j = 0; j < 2; j++) {
                float d0 = acc[mb][j][0], d1 = acc[mb][j][1];
                float d2 = acc[mb][j][2], d3 = acc[mb][j][3];
                float x = __shfl_xor_sync(0xffffffffu, even ? d2 : d0, 1);
                float y = __shfl_xor_sync(0xffffffffu, even ? d3 : d1, 1);
                int r   = rbase + mb * 16;
                int ugl = wc * 4 + j * 2 + ((lane & 3) >> 1);
                float gi = even ? d0 : x;
                float gf = even ? d1 : y;
                float gg = even ? x : d2;
                float go = even ? y : d3;
                float4 z;
                if (t == 0) z = *(const float4*)(g_Z0 + (size_t)(m0 + r) * G4_ + n0 + ugl * 4);
                else        z = zr[mb * 2 + j];
                gi += z.x; gf += z.y; gg += z.z; go += z.w;
                float c  = creg[mb * 2 + j];
                float cn = fsigm(gf) * c + fsigm(gi) * ftanh(gg);
                float hn = fsigm(go) * ftanh(cn);
                creg[mb * 2 + j] = cn;
                int ci = (m0 + r) * H_ + u0 + ugl;
                __nv_bfloat16 hi = __float2bfloat16_rn(hn);
                g_Hhi[toff + ci] = hi;
                g_Hlo[toff + ci] = __float2bfloat16_rn(hn - __bfloat162float(hi));
            }
        }

        // ---- per-m-group barrier (skip after last step) ----
        if (t < LEN_ - 1) {
            __syncthreads();
            if (tid == 0) {
                __threadfence();
                atomicAdd(&g_barc[mg * 64], 1u);
                unsigned int tgt = (unsigned int)(t + 1) * 32u;
                while (*(volatile unsigned int*)&g_barc[mg * 64] < tgt) { }
                __threadfence();
            }
            __syncthreads();
        }
    }
}

// ---------------------------------------------------------------------------
// k_fc_mma: out[r=t*512+b, j] = (Hhi+Hlo)[r,:] @ Wfc^T[:,j] + b_fc[j]
// HMMA GEMM, 3 bf16 splits. 256 CTAs x 128 rows. W_fc hi/lo smem-resident
// (160KB, 80 padded n-rows), double-buffered cp.async A.
// 8 warps: warp = one m16 block, 10 n8 frags.
// ---------------------------------------------------------------------------
#define FCB_  163840                      // B: 2 splits x 8 chunks x 80 rows x 128B
#define FCA1  32768                       // one A buffer (hi 16KB + lo 16KB)
#define FC_SMEM (FCB_ + 2 * FCA1)         // 229376

__global__ __launch_bounds__(256) void k_fc_mma(float* __restrict__ out,
                                                const float* __restrict__ b_fc) {
    extern __shared__ __align__(16) char smem[];
    uint32_t sB = smem_u32(smem);
    uint32_t sA = sB + FCB_;

    int tid = threadIdx.x, lane = tid & 31, wid = tid >> 5;
    int m0 = (int)blockIdx.x * 128;

    // ---- load resident B (W_fc hi/lo, 80 rows, swizzled) ----
    for (int u = tid; u < 10240; u += 256) {
        int s = u / 5120, rem = u % 5120;
        int kb = rem / 640, r2 = rem % 640, row = r2 >> 3, j = r2 & 7;
        const __nv_bfloat16* src = (s ? g_Wfclo : g_Wfchi) + (size_t)row * H_ + kb * 64 + j * 8;
        uint32_t dst = sB + (uint32_t)(s * 81920 + kb * 10240 + row * 128 + ((j ^ (row & 7)) << 4));
        cp16(dst, src);
    }
    cp_commit();
    cp_wait0();
    __syncthreads();

    int arow = tid >> 1, ahalf = tid & 1;
    auto issueA = [&](int kb, int buf) {
        const __nv_bfloat16* ah = g_Hhi + (size_t)(m0 + arow) * H_ + kb * 64;
        const __nv_bfloat16* al = g_Hlo + (size_t)(m0 + arow) * H_ + kb * 64;
        uint32_t ad = sA + (uint32_t)(buf * FCA1 + arow * 128);
        #pragma unroll
        for (int jj = 0; jj < 4; jj++) {
            int j = ahalf * 4 + jj;
            uint32_t off = (uint32_t)((j ^ (arow & 7)) << 4);
            cp16(ad + off, ah + j * 8);
            cp16(ad + 16384u + off, al + j * 8);
        }
        cp_commit();
    };

    float acc[10][4];
    #pragma unroll
    for (int nb = 0; nb < 10; nb++)
        #pragma unroll
        for (int q = 0; q < 4; q++) acc[nb][q] = 0.0f;

    int lrow = wid * 16 + (lane & 15);
    int lch = lane >> 4;

    issueA(0, 0);
    issueA(1, 1);

    #pragma unroll 1
    for (int kb = 0; kb < 8; kb++) {
        if (kb < 7) cp_wait1(); else cp_wait0();
        __syncthreads();

        uint32_t aB = sA + (uint32_t)((kb & 1) * FCA1);
        uint32_t bB = sB + (uint32_t)(kb * 10240);
        #pragma unroll
        for (int kc = 0; kc < 4; kc++) {
            uint32_t ah[4], al[4], bh[5][4], bl[5][4];
            {
                uint32_t off = (uint32_t)lrow * 128u
                             + (uint32_t)(((2 * kc + lch) ^ (lrow & 7)) << 4);
                ldsm_x4(ah[0], ah[1], ah[2], ah[3], aB + off);
                ldsm_x4(al[0], al[1], al[2], al[3], aB + 16384u + off);
            }
            #pragma unroll
            for (int q = 0; q < 5; q++) {
                int row = q * 16 + (lane & 15);
                uint32_t off = (uint32_t)row * 128u
                             + (uint32_t)(((2 * kc + lch) ^ (row & 7)) << 4);
                ldsm_x4(bh[q][0], bh[q][1], bh[q][2], bh[q][3], bB + off);
                ldsm_x4(bl[q][0], bl[q][1], bl[q][2], bl[q][3], bB + 81920u + off);
            }
            #pragma unroll
            for (int q = 0; q < 5; q++)
                #pragma unroll
                for (int par = 0; par < 2; par++) {
                    int nb = q * 2 + par;
                    mma16816(acc[nb][0], acc[nb][1], acc[nb][2], acc[nb][3],
                             ah[0], ah[1], ah[2], ah[3], bh[q][par], bh[q][par + 2]);
                    mma16816(acc[nb][0], acc[nb][1], acc[nb][2], acc[nb][3],
                             al[0], al[1], al[2], al[3], bh[q][par], bh[q][par + 2]);
                    mma16816(acc[nb][0], acc[nb][1], acc[nb][2], acc[nb][3],
                             ah[0], ah[1], ah[2], ah[3], bl[q][par], bl[q][par + 2]);
                }
        }
        __syncthreads();
        if (kb + 2 < 8) issueA(kb + 2, kb & 1);
    }

    // ---- epilogue: bias + scatter store (out[b][t][j], r = t*512+b) ----
    int r0 = m0 + wid * 16 + (lane >> 2);
    int r1 = r0 + 8;
    int t0 = r0 >> 9, b0 = r0 & 511;
    int t1 = r1 >> 9, b1 = r1 & 511;
    float* o0 = out + ((size_t)b0 * LEN_ + t0) * OUT_;
    float* o1 = out + ((size_t)b1 * LEN_ + t1) * OUT_;
    #pragma unroll
    for (int nb = 0; nb < 10; nb++) {
        int j0 = nb * 8 + (lane & 3) * 2;
        if (j0 < OUT_) {
            float bz0 = __ldg(b_fc + j0), bz1 = __ldg(b_fc + j0 + 1);
            *(float2*)(o0 + j0) = make_float2(acc[nb][0] + bz0, acc[nb][1] + bz1);
            *(float2*)(o1 + j0) = make_float2(acc[nb][2] + bz0, acc[nb][3] + bz1);
        }
    }
}

// ---------------------------------------------------------------------------
extern "C" void kernel_launch(void* const* d_in, const int* in_sizes, int n_in,
                              void* d_out, int out_size) {
    int off = (n_in >= 13) ? 1 : 0;   // 'length' scalar present
    const float* inputs = (const float*)d_in[0];
    const int*   labels = (const int*)  d_in[1];
    const float* W_ih  = (const float*)d_in[2 + off];
    const float* W_hh  = (const float*)d_in[3 + off];
    const float* b_ih  = (const float*)d_in[4 + off];
    const float* b_hh  = (const float*)d_in[5 + off];
    const float* W_fc  = (const float*)d_in[6 + off];
    const float* b_fc  = (const float*)d_in[7 + off];
    const float* W_inh = (const float*)d_in[8 + off];
    const float* b_inh = (const float*)d_in[9 + off];
    const float* W_inc = (const float*)d_in[10 + off];
    const float* b_inc = (const float*)d_in[11 + off];
    float* out = (float*)d_out;

    cudaFuncSetAttribute(k_persist, cudaFuncAttributeMaxDynamicSharedMemorySize, PS_SMEM);
    cudaFuncSetAttribute(k_fc_mma, cudaFuncAttributeMaxDynamicSharedMemorySize, FC_SMEM);

    k_prep_a<<<B_ + 64, 256>>>(inputs, W_inh, b_inh, W_inc, b_inc, W_fc, W_ih);
    k_prep_Z<<<dim3(8, 64), 256>>>(b_ih, b_hh, b_fc, labels);
    k_prep_W<<<dim3(8, 64), 256>>>(W_hh, W_fc);
    k_prep_fc<<<80, 256>>>(W_fc);

    k_persist<<<NCTA_, 512, PS_SMEM>>>();

    k_fc_mma<<<256, 256, FC_SMEM>>>(out, b_fc);
}